// round 5
// baseline (speedup 1.0000x reference)
#include <cuda_runtime.h>
#include <cuda_bf16.h>

// Problem constants (fixed by reference): B=512, T=1024, IN=1, H=64
#define BSZ   512
#define TLEN  1024
#define HDIM  64
#define G4    4                 // batches per block
#define NTHR  256
#define NBLK  (BSZ / G4)        // 128 blocks

// Packed fp32x2 FMA (Blackwell FFMA2) — lanewise: lo=lo*lo+lo, hi=hi*hi+hi
__device__ __forceinline__ unsigned long long fma2(unsigned long long a,
                                                   unsigned long long b,
                                                   unsigned long long c) {
    unsigned long long d;
    asm("fma.rn.f32x2 %0, %1, %2, %3;" : "=l"(d) : "l"(a), "l"(b), "l"(c));
    return d;
}

__device__ __forceinline__ float lo_add_hi(unsigned long long v) {
    float2 f = *reinterpret_cast<float2*>(&v);
    return f.x + f.y;
}

__device__ __forceinline__ unsigned long long pack2(float lo, float hi) {
    return ((unsigned long long)__float_as_uint(hi) << 32) | __float_as_uint(lo);
}

// sigmoid/tanh via MUFU.EX2 + approx-div. ex2.approx rel err ~2^-22 -> plenty
// for rel_err<1e-3 over 1024 steps. Saturates correctly at +-inf.
__device__ __forceinline__ float fast_sigmoid(float x) {
    return __fdividef(1.0f, 1.0f + __expf(-x));
}
__device__ __forceinline__ float fast_tanh(float x) {
    return 1.0f - __fdividef(2.0f, 1.0f + __expf(2.0f * x));
}

__global__ void __launch_bounds__(NTHR, 1) qlstm_kernel(
    const float* __restrict__ x,      // [B, T, 1]
    const float* __restrict__ W_ih,   // [256, 1]
    const float* __restrict__ W_hh,   // [256, 64]
    const float* __restrict__ b_ih,   // [256]
    const float* __restrict__ b_hh,   // [256]
    const float* __restrict__ W_lin,  // [1, 64]
    const float* __restrict__ b_lin,  // [1]
    float* __restrict__ out)          // [B]
{
    __shared__ __align__(16) float xs[G4 * TLEN];    // 16 KB: staged x rows
    __shared__ __align__(16) float hbuf[G4 * HDIM];  // 1 KB : h state
    __shared__ __align__(16) float act[G4 * 256];    // 4 KB : activated gates

    const int tid   = threadIdx.x;
    const int bbase = blockIdx.x * G4;
    const int kg    = tid & 7;    // k-group: columns kg*8 .. kg*8+7
    const int jg    = tid >> 3;   // j-group: rows    jg*8 .. jg*8+7

    // ---- stage x (coalesced, one-time) ----
    for (int idx = tid; idx < G4 * TLEN; idx += NTHR)
        xs[idx] = x[(bbase + (idx >> 10)) * TLEN + (idx & (TLEN - 1))];

    // ---- W_hh 8x8 tile -> registers, packed in k-pairs (64 regs) ----
    unsigned long long w2[8][4];
    #pragma unroll
    for (int jj = 0; jj < 8; jj++) {
        const float2* wp = reinterpret_cast<const float2*>(
            W_hh + (jg * 8 + jj) * HDIM + kg * 8);
        #pragma unroll
        for (int kk = 0; kk < 4; kk++) {
            float2 v = wp[kk];
            w2[jj][kk] = pack2(v.x, v.y);
        }
    }

    // Final gate owned by this thread after the butterfly: jj = brev3(kg)
    const int brev = ((kg & 1) << 2) | (kg & 2) | (kg >> 2);
    const int jf   = jg * 8 + brev;          // gate row 0..255
    const float wih   = W_ih[jf];
    const float biasv = b_ih[jf] + b_hh[jf];
    const int   grp   = jf >> 6;             // 0=i 1=f 2=g(tanh) 3=o

    // update-phase assignment: thread -> (batch ug, hidden unit um); c in reg
    const int um = tid & 63;
    const int ug = tid >> 6;
    float c = 0.0f;

    if (tid < G4 * HDIM) hbuf[tid] = 0.0f;
    __syncthreads();

    const unsigned FULL = 0xffffffffu;
    const int b0 = kg & 1, b1 = (kg >> 1) & 1, b2 = (kg >> 2) & 1;

    for (int t = 0; t < TLEN; t++) {
        #pragma unroll
        for (int g = 0; g < G4; g++) {
            // h slice (8 floats) as 4 packed pairs; broadcast-heavy LDS.128
            const ulonglong2* hp = reinterpret_cast<const ulonglong2*>(
                hbuf + g * HDIM + kg * 8);
            ulonglong2 ha = hp[0];
            ulonglong2 hb = hp[1];
            unsigned long long h2[4] = {ha.x, ha.y, hb.x, hb.y};

            // 8 partial dot products, packed fp32x2 (32 FFMA2)
            float p[8];
            #pragma unroll
            for (int jj = 0; jj < 8; jj++) {
                unsigned long long acc = 0ull;   // pack2(0,0)
                #pragma unroll
                for (int kk = 0; kk < 4; kk++)
                    acc = fma2(w2[jj][kk], h2[kk], acc);
                p[jj] = lo_add_hi(acc);
            }

            // 7-shuffle butterfly over the 8-lane octet (kg dimension);
            // each stage keeps half the values, ships the other half.
            float q[4];
            #pragma unroll
            for (int i = 0; i < 4; i++) {
                float keep = b0 ? p[i + 4] : p[i];
                float send = b0 ? p[i]     : p[i + 4];
                q[i] = keep + __shfl_xor_sync(FULL, send, 1);
            }
            float r0, r1;
            {
                float keep = b1 ? q[2] : q[0];
                float send = b1 ? q[0] : q[2];
                r0 = keep + __shfl_xor_sync(FULL, send, 2);
                keep = b1 ? q[3] : q[1];
                send = b1 ? q[1] : q[3];
                r1 = keep + __shfl_xor_sync(FULL, send, 2);
            }
            float gate;
            {
                float keep = b2 ? r1 : r0;
                float send = b2 ? r0 : r1;
                gate = keep + __shfl_xor_sync(FULL, send, 4);
            }

            // add x-term + bias, activate, publish
            float a  = fmaf(xs[g * TLEN + t], wih, gate + biasv);
            float av = (grp == 2) ? fast_tanh(a) : fast_sigmoid(a);
            act[g * 256 + jf] = av;
        }
        __syncthreads();

        // ---- state update: thread (ug, um); c stays in register ----
        {
            const float* ab = act + ug * 256 + um;
            float ai = ab[0];
            float af = ab[64];
            float ag = ab[128];
            float ao = ab[192];
            c = fmaf(af, c, ai * ag);
            hbuf[ug * HDIM + um] = ao * fast_tanh(c);
        }
        __syncthreads();
    }

    // ---- epilogue: out[b] = h_final . W_lin + b_lin ----
    const int wid = tid >> 5, lane = tid & 31;
    if (wid < G4) {
        float v = fmaf(hbuf[wid * HDIM + lane], W_lin[lane],
                       hbuf[wid * HDIM + lane + 32] * W_lin[lane + 32]);
        #pragma unroll
        for (int m = 16; m >= 1; m >>= 1)
            v += __shfl_xor_sync(FULL, v, m);
        if (lane == 0) out[bbase + wid] = v + b_lin[0];
    }
}

extern "C" void kernel_launch(void* const* d_in, const int* in_sizes, int n_in,
                              void* d_out, int out_size) {
    const float* x     = (const float*)d_in[0];
    const float* W_ih  = (const float*)d_in[1];
    const float* W_hh  = (const float*)d_in[2];
    const float* b_ih  = (const float*)d_in[3];
    const float* b_hh  = (const float*)d_in[4];
    const float* W_lin = (const float*)d_in[5];
    const float* b_lin = (const float*)d_in[6];
    float* out = (float*)d_out;

    qlstm_kernel<<<NBLK, NTHR>>>(x, W_ih, W_hh, b_ih, b_hh, W_lin, b_lin, out);
}

// round 7
// speedup vs baseline: 1.4166x; 1.4166x over previous
#include <cuda_runtime.h>
#include <cuda_bf16.h>

// B=512, T=1024, IN=1, H=64
#define TLEN 1024
#define HDIM 64
#define GB   2              // batches per block
#define NTHR 128            // 64 units x 2 k-splits
#define NBLK 256            // 512 / GB  -> 2 co-resident blocks per SM

__device__ __forceinline__ unsigned long long fma2(unsigned long long a,
                                                   unsigned long long b,
                                                   unsigned long long c) {
    unsigned long long d;
    asm("fma.rn.f32x2 %0, %1, %2, %3;" : "=l"(d) : "l"(a), "l"(b), "l"(c));
    return d;
}
__device__ __forceinline__ unsigned long long pack2(float lo, float hi) {
    unsigned long long r;
    asm("mov.b64 %0, {%1, %2};" : "=l"(r) : "f"(lo), "f"(hi));
    return r;
}
__device__ __forceinline__ float lo_add_hi(unsigned long long v) {
    float lo, hi;
    asm("mov.b64 {%0, %1}, %2;" : "=f"(lo), "=f"(hi) : "l"(v));
    return lo + hi;
}
__device__ __forceinline__ float ex2f(float x) {
    float r; asm("ex2.approx.f32 %0, %1;" : "=f"(r) : "f"(x)); return r;
}
__device__ __forceinline__ float rcpf(float x) {
    float r; asm("rcp.approx.f32 %0, %1;" : "=f"(r) : "f"(x)); return r;
}
// Gate pre-activations arrive PRE-SCALED by -log2(e) (sigmoid rows) or
// -2*log2(e) (tanh row), so:
//   sigmoid(a) = 1/(1+ex2(z)),  tanh(a) = 2/(1+ex2(z)) - 1

#define NLOG2E  1.44269504f
#define N2LOG2E 2.88539008f

__global__ void __launch_bounds__(NTHR, 2) qlstm_kernel(
    const float* __restrict__ x,      // [512, 1024, 1]
    const float* __restrict__ W_ih,   // [256, 1]
    const float* __restrict__ W_hh,   // [256, 64]
    const float* __restrict__ b_ih,   // [256]
    const float* __restrict__ b_hh,   // [256]
    const float* __restrict__ W_lin,  // [1, 64]
    const float* __restrict__ b_lin,  // [1]
    float* __restrict__ out)          // [512]
{
    __shared__ __align__(16) float xs[GB][TLEN];       // 8 KB
    __shared__ __align__(16) float hsm[2][GB][HDIM];   // 1 KB, double-buffered

    const int tid = threadIdx.x;
    const int s   = tid & 1;      // k-split half: cols [32s, 32s+32)
    const int m   = tid >> 1;     // hidden unit 0..63
    const int bb  = blockIdx.x * GB;

    // ---- stage x (coalesced, one-time) ----
    for (int i = tid; i < GB * TLEN; i += NTHR)
        xs[i >> 10][i & (TLEN - 1)] = x[(bb + (i >> 10)) * TLEN + (i & (TLEN - 1))];

    // ---- W_hh rows {m, 64+m, 128+m, 192+m}, k-half s -> regs, prescaled ----
    unsigned long long w2[4][16];          // 128 regs
    float wih[4], bia[4];
    #pragma unroll
    for (int q = 0; q < 4; q++) {
        const float scl = (q == 2) ? -N2LOG2E : -NLOG2E;
        const int row = q * 64 + m;
        const float4* wr = reinterpret_cast<const float4*>(W_hh + row * HDIM + 32 * s);
        #pragma unroll
        for (int kk = 0; kk < 8; kk++) {
            float4 v = wr[kk];
            w2[q][2 * kk]     = pack2(scl * v.x, scl * v.y);
            w2[q][2 * kk + 1] = pack2(scl * v.z, scl * v.w);
        }
        wih[q] = scl * W_ih[row];
        bia[q] = scl * (b_ih[row] + b_hh[row]);
    }

    for (int i = tid; i < 2 * GB * HDIM; i += NTHR)
        reinterpret_cast<float*>(hsm)[i] = 0.0f;

    float c[GB];
    #pragma unroll
    for (int g = 0; g < GB; g++) c[g] = 0.0f;

    __syncthreads();

    const unsigned FULL = 0xffffffffu;
    // fold bias + x-term into exactly ONE of the two k-split accumulators
    const float foldsel = (s == 0) ? 1.0f : 0.0f;

    auto step = [&](int t, const float (*hin)[HDIM], float (*hout)[HDIM]) {
        #pragma unroll
        for (int g = 0; g < GB; g++) {
            // h slice (32 floats) -> 16 packed pairs (broadcast LDS.128)
            const float4* hb = reinterpret_cast<const float4*>(hin[g] + 32 * s);
            unsigned long long h2[16];
            #pragma unroll
            for (int kk = 0; kk < 8; kk++) {
                float4 v = hb[kk];
                h2[2 * kk]     = pack2(v.x, v.y);
                h2[2 * kk + 1] = pack2(v.z, v.w);
            }
            const float xv = xs[g][t];
            // bias + x-term folded into accumulator init (lo lane, s==0 only)
            unsigned long long acc[4];
            #pragma unroll
            for (int q = 0; q < 4; q++)
                acc[q] = pack2(foldsel * fmaf(xv, wih[q], bia[q]), 0.0f);
            // 4 gates x 16-deep packed FMA chains
            #pragma unroll
            for (int kk = 0; kk < 16; kk++) {
                #pragma unroll
                for (int q = 0; q < 4; q++)
                    acc[q] = fma2(w2[q][kk], h2[kk], acc[q]);
            }
            // single shuffle to merge the partner k-half; both lanes get total
            float z[4];
            #pragma unroll
            for (int q = 0; q < 4; q++) {
                float v = lo_add_hi(acc[q]);
                z[q] = v + __shfl_xor_sync(FULL, v, 1);
            }
            const float gi = rcpf(1.0f + ex2f(z[0]));
            const float gf = rcpf(1.0f + ex2f(z[1]));
            const float gg = fmaf(2.0f, rcpf(1.0f + ex2f(z[2])), -1.0f);
            const float go = rcpf(1.0f + ex2f(z[3]));
            c[g] = fmaf(gf, c[g], gi * gg);
            const float tc = fmaf(2.0f, rcpf(1.0f + ex2f(-N2LOG2E * c[g])), -1.0f);
            if (s == 0) hout[g][m] = go * tc;
        }
    };

    #pragma unroll 1
    for (int t = 0; t < TLEN; t += 2) {
        step(t,     hsm[0], hsm[1]);
        __syncthreads();
        step(t + 1, hsm[1], hsm[0]);
        __syncthreads();
    }
    // t=1023 (odd) wrote hsm[0] -> final h lives in hsm[0]

    // ---- epilogue: out[b] = h_final . W_lin + b_lin ----
    const int w = tid >> 5, lane = tid & 31;
    if (w < GB) {
        const float* hf = hsm[0][w];
        float v = fmaf(hf[lane], W_lin[lane], hf[lane + 32] * W_lin[lane + 32]);
        #pragma unroll
        for (int d = 16; d >= 1; d >>= 1)
            v += __shfl_xor_sync(FULL, v, d);
        if (lane == 0) out[bb + w] = v + b_lin[0];
    }
}

extern "C" void kernel_launch(void* const* d_in, const int* in_sizes, int n_in,
                              void* d_out, int out_size) {
    const float* x     = (const float*)d_in[0];
    const float* W_ih  = (const float*)d_in[1];
    const float* W_hh  = (const float*)d_in[2];
    const float* b_ih  = (const float*)d_in[3];
    const float* b_hh  = (const float*)d_in[4];
    const float* W_lin = (const float*)d_in[5];
    const float* b_lin = (const float*)d_in[6];
    float* out = (float*)d_out;

    qlstm_kernel<<<NBLK, NTHR>>>(x, W_ih, W_hh, b_ih, b_hh, W_lin, b_lin, out);
}

// round 8
// speedup vs baseline: 1.4452x; 1.0202x over previous
#include <cuda_runtime.h>
#include <cuda_bf16.h>

// B=512, T=1024, IN=1, H=64
#define TLEN 1024
#define HDIM 64
#define GB   2              // batches per block (weights shared across both)
#define NTHR 128            // 64 units x 2 gate-pairs
#define NBLK 256            // 512 / GB -> 2 co-resident blocks per SM

typedef unsigned long long u64;

__device__ __forceinline__ u64 fma2(u64 a, u64 b, u64 c) {
    u64 d;
    asm("fma.rn.f32x2 %0, %1, %2, %3;" : "=l"(d) : "l"(a), "l"(b), "l"(c));
    return d;
}
__device__ __forceinline__ u64 pack2(float lo, float hi) {
    u64 r;
    asm("mov.b64 %0, {%1, %2};" : "=l"(r) : "f"(lo), "f"(hi));
    return r;
}
__device__ __forceinline__ float lo_add_hi(u64 v) {
    float lo, hi;
    asm("mov.b64 {%0, %1}, %2;" : "=f"(lo), "=f"(hi) : "l"(v));
    return lo + hi;
}
__device__ __forceinline__ float ex2f(float x) {
    float r; asm("ex2.approx.f32 %0, %1;" : "=f"(r) : "f"(x)); return r;
}
__device__ __forceinline__ float rcpf(float x) {
    float r; asm("rcp.approx.f32 %0, %1;" : "=f"(r) : "f"(x)); return r;
}
// Gate rows are PRE-SCALED by -log2(e) (sigmoid rows) or -2*log2(e) (tanh row):
//   sigmoid(a) = 1/(1+ex2(z));   tanh(a) = 2/(1+ex2(z)) - 1
#define NLOG2E  1.44269504f
#define N2LOG2E 2.88539008f

__global__ void __launch_bounds__(NTHR, 2) qlstm_kernel(
    const float* __restrict__ x,      // [512, 1024, 1]
    const float* __restrict__ W_ih,   // [256, 1]
    const float* __restrict__ W_hh,   // [256, 64]
    const float* __restrict__ b_ih,   // [256]
    const float* __restrict__ b_hh,   // [256]
    const float* __restrict__ W_lin,  // [1, 64]
    const float* __restrict__ b_lin,  // [1]
    float* __restrict__ out)          // [512]
{
    __shared__ __align__(16) float xs[GB][TLEN];       // 8 KB
    __shared__ __align__(16) float hsm[2][GB][HDIM];   // 1 KB, double-buffered

    const int tid = threadIdx.x;
    const int p   = tid & 1;      // 0 -> gates {i,f}; 1 -> gates {g,o}
    const int m   = tid >> 1;     // hidden unit 0..63
    const int bb  = blockIdx.x * GB;

    // ---- stage x (coalesced, one-time) ----
    for (int i = tid; i < GB * TLEN; i += NTHR)
        xs[i >> 10][i & (TLEN - 1)] = x[(bb + (i >> 10)) * TLEN + (i & (TLEN - 1))];

    // ---- 2 full-K W_hh rows -> regs, prescaled (128 regs) ----
    const int   r0   = p ? 128 + m : m;        // g-row  : i-row
    const int   r1   = p ? 192 + m : 64 + m;   // o-row  : f-row
    const float scl0 = p ? -N2LOG2E : -NLOG2E; // tanh row gets 2x scale
    const float scl1 = -NLOG2E;

    u64 w0[32], w1[32];
    {
        const float4* a = reinterpret_cast<const float4*>(W_hh + r0 * HDIM);
        const float4* b = reinterpret_cast<const float4*>(W_hh + r1 * HDIM);
        #pragma unroll
        for (int k = 0; k < 16; k++) {
            float4 v = a[k];
            w0[2 * k]     = pack2(scl0 * v.x, scl0 * v.y);
            w0[2 * k + 1] = pack2(scl0 * v.z, scl0 * v.w);
            float4 u = b[k];
            w1[2 * k]     = pack2(scl1 * u.x, scl1 * u.y);
            w1[2 * k + 1] = pack2(scl1 * u.z, scl1 * u.w);
        }
    }
    const float wih0 = scl0 * W_ih[r0], bia0 = scl0 * (b_ih[r0] + b_hh[r0]);
    const float wih1 = scl1 * W_ih[r1], bia1 = scl1 * (b_ih[r1] + b_hh[r1]);

    for (int i = tid; i < 2 * GB * HDIM; i += NTHR)
        reinterpret_cast<float*>(hsm)[i] = 0.0f;

    float c[GB] = {0.0f, 0.0f};   // live in p==0 lanes (p==1 copy is dead)
    __syncthreads();

    const unsigned FULL = 0xffffffffu;

    auto step = [&](int t, const float (*hin)[HDIM], float (*hout)[HDIM]) {
        #pragma unroll
        for (int g = 0; g < GB; g++) {
            // full h (64 floats) as 32 packed pairs; uniform (broadcast) LDS.128
            const ulonglong2* hp = reinterpret_cast<const ulonglong2*>(hin[g]);
            u64 h2[32];
            #pragma unroll
            for (int k = 0; k < 16; k++) {
                ulonglong2 v = hp[k];
                h2[2 * k] = v.x; h2[2 * k + 1] = v.y;
            }
            const float xv = xs[g][t];
            // bias + x folded once (full-K owner => no double count)
            u64 acc0 = pack2(fmaf(xv, wih0, bia0), 0.0f);
            u64 acc1 = pack2(fmaf(xv, wih1, bia1), 0.0f);
            #pragma unroll
            for (int k = 0; k < 32; k++) {
                acc0 = fma2(w0[k], h2[k], acc0);
                acc1 = fma2(w1[k], h2[k], acc1);
            }
            const float z0 = lo_add_hi(acc0);   // p0: z_i   p1: z_g
            const float z1 = lo_add_hi(acc1);   // p0: z_f   p1: z_o
            const float a0 = rcpf(1.0f + ex2f(z0));  // p0: sig(i)  p1: (tanh(g)+1)/2
            const float a1 = rcpf(1.0f + ex2f(z1));  // p0: sig(f)  p1: sig(o)
            const float tga = fmaf(2.0f, a0, -1.0f); // p1: tanh(g)

            // exchange: p0 receives tanh(g); p1 receives sig(i) (dead)
            const float trec = __shfl_xor_sync(FULL, p ? tga : a0, 1);
            // p0: c = sig(f)*c + sig(i)*tanh(g)   (p1 lane: finite garbage)
            c[g] = fmaf(a1, c[g], a0 * trec);
            const float tc = fmaf(2.0f, rcpf(1.0f + ex2f(-N2LOG2E * c[g])), -1.0f);
            // exchange: p1 receives tanh(c) from p0
            const float tcx = __shfl_xor_sync(FULL, tc, 1);
            if (p) hout[g][m] = a1 * tcx;       // h = sig(o) * tanh(c)
        }
    };

    #pragma unroll 1
    for (int t = 0; t < TLEN; t += 2) {
        step(t,     hsm[0], hsm[1]);
        __syncthreads();
        step(t + 1, hsm[1], hsm[0]);
        __syncthreads();
    }
    // t=1023 (odd) wrote hsm[0] -> final h in hsm[0]

    // ---- epilogue: out[b] = h_final . W_lin + b_lin ----
    const int w = tid >> 5, lane = tid & 31;
    if (w < GB) {
        const float* hf = hsm[0][w];
        float v = fmaf(hf[lane], W_lin[lane], hf[lane + 32] * W_lin[lane + 32]);
        #pragma unroll
        for (int d = 16; d >= 1; d >>= 1)
            v += __shfl_xor_sync(FULL, v, d);
        if (lane == 0) out[bb + w] = v + b_lin[0];
    }
}

extern "C" void kernel_launch(void* const* d_in, const int* in_sizes, int n_in,
                              void* d_out, int out_size) {
    const float* x     = (const float*)d_in[0];
    const float* W_ih  = (const float*)d_in[1];
    const float* W_hh  = (const float*)d_in[2];
    const float* b_ih  = (const float*)d_in[3];
    const float* b_hh  = (const float*)d_in[4];
    const float* W_lin = (const float*)d_in[5];
    const float* b_lin = (const float*)d_in[6];
    float* out = (float*)d_out;

    qlstm_kernel<<<NBLK, NTHR>>>(x, W_ih, W_hh, b_ih, b_hh, W_lin, b_lin, out);
}